// round 14
// baseline (speedup 1.0000x reference)
#include <cuda_runtime.h>
#include <cuda_bf16.h>
#include <cstdint>

#define Dm   192
#define DIN  384
#define NSz  16
#define DTRz 12
#define KC   4
#define CIN  96
#define Bz   2
#define L0z  3136
#define L1z  784
#define BL0  (Bz*L0z)
#define NCHMAX 49
#define ASTR 40   // smem row stride in bf16 elements (conflict-free for ldmatrix)

// ---------------- static scratch (no allocs allowed) ----------------
__device__ float g_x   [Bz*L0z*Dm];      // activation (B, L, D)
__device__ float g_pool[Bz*L1z*Dm];
__device__ float g_xz  [BL0*2*DIN];
__device__ float g_proj[BL0*44];
__device__ float g_dt  [BL0*DIN];
__device__ float g_blk [BL0*Dm];
__device__ float g_Pc  [Bz*NCHMAX*DIN*NSz];
__device__ float g_Hc  [Bz*NCHMAX*DIN*NSz];
__device__ float g_Hin [Bz*NCHMAX*DIN*NSz];
__device__ float g_b2  [Dm];
// bf16 hi/lo operand buffers
__device__ __align__(16) __nv_bfloat16 g_hh [BL0*Dm];
__device__ __align__(16) __nv_bfloat16 g_hl [BL0*Dm];
__device__ __align__(16) __nv_bfloat16 g_xih[BL0*DIN];   // also stem xT (BL0 x 96)
__device__ __align__(16) __nv_bfloat16 g_xil[BL0*DIN];
__device__ __align__(16) __nv_bfloat16 g_yh [BL0*DIN];
__device__ __align__(16) __nv_bfloat16 g_yl [BL0*DIN];
__device__ __align__(16) __nv_bfloat16 g_Winh[3*2*DIN*Dm];
__device__ __align__(16) __nv_bfloat16 g_Winl[3*2*DIN*Dm];
__device__ __align__(16) __nv_bfloat16 g_Wxh [3*44*DIN];
__device__ __align__(16) __nv_bfloat16 g_Wxl [3*44*DIN];
__device__ __align__(16) __nv_bfloat16 g_Wouth[3*Dm*DIN];
__device__ __align__(16) __nv_bfloat16 g_Woutl[3*Dm*DIN];
__device__ __align__(16) __nv_bfloat16 g_w2h[Dm*CIN];
__device__ __align__(16) __nv_bfloat16 g_w2l[Dm*CIN];

#define MMA_BF16(c, a, b)                                                     \
    asm volatile("mma.sync.aligned.m16n8k16.row.col.f32.bf16.bf16.f32 "       \
        "{%0,%1,%2,%3},{%4,%5,%6,%7},{%8,%9},{%0,%1,%2,%3};"                  \
        : "+f"((c)[0]), "+f"((c)[1]), "+f"((c)[2]), "+f"((c)[3])              \
        : "r"((a)[0]), "r"((a)[1]), "r"((a)[2]), "r"((a)[3]),                 \
          "r"((b)[0]), "r"((b)[1]))

#define LDSM_X4(r, addr)                                                      \
    asm volatile("ldmatrix.sync.aligned.m8n8.x4.shared.b16 {%0,%1,%2,%3}, [%4];" \
        : "=r"((r)[0]), "=r"((r)[1]), "=r"((r)[2]), "=r"((r)[3]) : "r"(addr))
#define LDSM_X2(r, addr)                                                      \
    asm volatile("ldmatrix.sync.aligned.m8n8.x2.shared.b16 {%0,%1}, [%2];"    \
        : "=r"((r)[0]), "=r"((r)[1]) : "r"(addr))

__device__ __forceinline__ uint32_t smem_u32(const void* p) {
    return (uint32_t)__cvta_generic_to_shared(p);
}
__device__ __forceinline__ void splitw(float v, __nv_bfloat16& h, __nv_bfloat16& l) {
    h = __float2bfloat16(v);
    l = __float2bfloat16(v - __bfloat162float(h));
}

// ============ pre-split bf16 GEMM: C = A(M,K)*B(N,K)^T + bias ============
// Single-buffer static SMEM (5 CTAs/SM), register-prefetch pipelining,
// ldmatrix fragments. BM=128, BN in {64,128}, BK=32, 256 threads (2m x 4n).
// Requires K%32==0, lda/ldb multiple of 8.
template<int BN>
__global__ __launch_bounds__(256) void bgemm_bf(
        const __nv_bfloat16* __restrict__ Ah, const __nv_bfloat16* __restrict__ Al, int lda,
        const __nv_bfloat16* __restrict__ Bh, const __nv_bfloat16* __restrict__ Bl, int ldb,
        const float* __restrict__ bias,
        float* __restrict__ C, int ldc,
        int M, int N, int K, int addC) {
    constexpr int J  = BN / 32;      // n-blocks per warp
    constexpr int JB = BN / 64;      // B staging chunks per thread
    __shared__ __align__(16) uint16_t sAh[128*ASTR];
    __shared__ __align__(16) uint16_t sAl[128*ASTR];
    __shared__ __align__(16) uint16_t sBh[BN*ASTR];
    __shared__ __align__(16) uint16_t sBl[BN*ASTR];

    int bm = blockIdx.y * 128, bn = blockIdx.x * BN;
    int tid  = threadIdx.x;
    int lane = tid & 31;
    int w    = tid >> 5;
    int m0 = (w & 1) * 64;
    int n0 = (w >> 1) * (BN/4);
    int gq = lane >> 2;
    int tq = lane & 3;

    float c[4][J][4];
    #pragma unroll
    for (int i = 0; i < 4; i++)
        #pragma unroll
        for (int j = 0; j < J; j++)
            #pragma unroll
            for (int t = 0; t < 4; t++) c[i][j][t] = 0.f;

    const uint4 z16 = make_uint4(0,0,0,0);
    uint4 pah[2], pal[2], pbh[JB], pbl[JB];

    auto ldA = [&](int k0) {
        #pragma unroll
        for (int it = 0; it < 2; it++) {
            int cidx = tid + it*256;
            int r = cidx >> 2, q = cidx & 3;       // r:0..127, q:0..3 (8 bf16 each)
            bool ok = (bm + r) < M;
            int gr = ok ? (bm + r) : (M - 1);
            size_t so = (size_t)gr*lda + k0 + q*8;
            pah[it] = ok ? *(const uint4*)(Ah + so) : z16;
            pal[it] = ok ? *(const uint4*)(Al + so) : z16;
        }
    };
    auto ldB = [&](int k0) {
        #pragma unroll
        for (int it = 0; it < JB; it++) {
            int cidx = tid + it*256;
            int r = cidx >> 2, q = cidx & 3;
            bool ok = (bn + r) < N;
            int gr = ok ? (bn + r) : (N - 1);
            size_t so = (size_t)gr*ldb + k0 + q*8;
            pbh[it] = ok ? *(const uint4*)(Bh + so) : z16;
            pbl[it] = ok ? *(const uint4*)(Bl + so) : z16;
        }
    };
    auto stA = [&]() {
        #pragma unroll
        for (int it = 0; it < 2; it++) {
            int cidx = tid + it*256;
            int r = cidx >> 2, q = cidx & 3;
            int off = r*ASTR + q*8;
            *(uint4*)(sAh + off) = pah[it];
            *(uint4*)(sAl + off) = pal[it];
        }
    };
    auto stB = [&]() {
        #pragma unroll
        for (int it = 0; it < JB; it++) {
            int cidx = tid + it*256;
            int r = cidx >> 2, q = cidx & 3;
            int off = r*ASTR + q*8;
            *(uint4*)(sBh + off) = pbh[it];
            *(uint4*)(sBl + off) = pbl[it];
        }
    };

    // per-thread ldmatrix base offsets (canonical m16n8k16 fragment layout)
    int lr = lane & 15;
    int lk = (lane >> 4) << 3;
    int br = lane & 7;
    int bk = ((lane >> 3) & 1) << 3;
    uint32_t pAh0 = smem_u32(sAh) + (uint32_t)((m0 + lr)*ASTR + lk)*2;
    uint32_t pAl0 = smem_u32(sAl) + (uint32_t)((m0 + lr)*ASTR + lk)*2;
    uint32_t pBh0 = smem_u32(sBh) + (uint32_t)((n0 + br)*ASTR + bk)*2;
    uint32_t pBl0 = smem_u32(sBl) + (uint32_t)((n0 + br)*ASTR + bk)*2;

    int nst = K / 32;
    ldA(0); ldB(0);
    for (int s = 0; s < nst; s++) {
        stA(); stB();
        __syncthreads();
        if (s + 1 < nst) { ldA((s+1)*32); ldB((s+1)*32); }   // LDG overlaps MMA loop
        #pragma unroll
        for (int ks = 0; ks < 32; ks += 16) {
            uint32_t ah[4][4], al[4][4], bh[J][2], bl[J][2];
            #pragma unroll
            for (int i = 0; i < 4; i++) {
                uint32_t o = (uint32_t)(i*16*ASTR + ks)*2;
                LDSM_X4(ah[i], pAh0 + o);
                LDSM_X4(al[i], pAl0 + o);
            }
            #pragma unroll
            for (int j = 0; j < J; j++) {
                uint32_t o = (uint32_t)(j*8*ASTR + ks)*2;
                LDSM_X2(bh[j], pBh0 + o);
                LDSM_X2(bl[j], pBl0 + o);
            }
            #pragma unroll
            for (int i = 0; i < 4; i++)
                #pragma unroll
                for (int j = 0; j < J; j++) {
                    MMA_BF16(c[i][j], ah[i], bh[j]);
                    MMA_BF16(c[i][j], al[i], bh[j]);
                    MMA_BF16(c[i][j], ah[i], bl[j]);
                }
        }
        __syncthreads();
    }

    // ---- epilogue ----
    #pragma unroll
    for (int i = 0; i < 4; i++) {
        #pragma unroll
        for (int j = 0; j < J; j++) {
            int n = bn + n0 + j*8 + tq*2;
            if (n >= N) continue;
            float b0 = bias ? bias[n]   : 0.f;
            float b1 = bias ? bias[n+1] : 0.f;
            #pragma unroll
            for (int hh = 0; hh < 2; hh++) {
                int gm = bm + m0 + i*16 + gq + hh*8;
                if (gm >= M) continue;
                float v0 = c[i][j][hh*2 + 0] + b0;
                float v1 = c[i][j][hh*2 + 1] + b1;
                float* cp = C + (size_t)gm*ldc + n;
                if (addC) {
                    float2 old = *(float2*)cp;
                    v0 += old.x; v1 += old.y;
                }
                *(float2*)cp = make_float2(v0, v1);
            }
        }
    }
}

// ============ fp32-input 3-term GEMM (dt-proj only, K=12) ============
__global__ __launch_bounds__(256) void bgemm_f(
        const float* __restrict__ A, int lda,
        const float* __restrict__ B, int ldb,
        const float* __restrict__ bias,
        float* __restrict__ C, int ldc,
        int M, int N, int K, int act) {
    constexpr int J = 2;
    __shared__ __align__(16) uint16_t sAh[128*ASTR];
    __shared__ __align__(16) uint16_t sAl[128*ASTR];
    __shared__ __align__(16) uint16_t sBh[64*ASTR];
    __shared__ __align__(16) uint16_t sBl[64*ASTR];
    int bm = blockIdx.y * 128, bn = blockIdx.x * 64;
    int tid  = threadIdx.x;
    int lane = tid & 31;
    int w    = tid >> 5;
    int m0 = (w & 1) * 64;
    int n0 = (w >> 1) * 16;
    int gq = lane >> 2;
    int tq = lane & 3;
    float c[4][J][4] = {};
    const float4 z4 = make_float4(0.f,0.f,0.f,0.f);

    for (int k0 = 0; k0 < K; k0 += 32) {
        #pragma unroll
        for (int it = 0; it < 4; it++) {
            int idx = tid + it*256;
            int r = idx >> 3, q = idx & 7;
            int gm = bm + r, gk = k0 + q*4;
            float4 v = (gm < M && gk < K) ? *(const float4*)(A + (size_t)gm*lda + gk) : z4;
            __nv_bfloat16 h0,l0h,h1,l1h,h2,l2h,h3,l3h;
            splitw(v.x,h0,l0h); splitw(v.y,h1,l1h); splitw(v.z,h2,l2h); splitw(v.w,h3,l3h);
            int off = r*ASTR + q*4;
            *(uint2*)(sAh+off) = make_uint2(
                (uint32_t)__bfloat16_as_ushort(h0) | ((uint32_t)__bfloat16_as_ushort(h1)<<16),
                (uint32_t)__bfloat16_as_ushort(h2) | ((uint32_t)__bfloat16_as_ushort(h3)<<16));
            *(uint2*)(sAl+off) = make_uint2(
                (uint32_t)__bfloat16_as_ushort(l0h) | ((uint32_t)__bfloat16_as_ushort(l1h)<<16),
                (uint32_t)__bfloat16_as_ushort(l2h) | ((uint32_t)__bfloat16_as_ushort(l3h)<<16));
        }
        #pragma unroll
        for (int it = 0; it < 2; it++) {
            int idx = tid + it*256;
            int r = idx >> 3, q = idx & 7;
            int gn = bn + r, gk = k0 + q*4;
            float4 v = (gn < N && gk < K) ? *(const float4*)(B + (size_t)gn*ldb + gk) : z4;
            __nv_bfloat16 h0,l0h,h1,l1h,h2,l2h,h3,l3h;
            splitw(v.x,h0,l0h); splitw(v.y,h1,l1h); splitw(v.z,h2,l2h); splitw(v.w,h3,l3h);
            int off = r*ASTR + q*4;
            *(uint2*)(sBh+off) = make_uint2(
                (uint32_t)__bfloat16_as_ushort(h0) | ((uint32_t)__bfloat16_as_ushort(h1)<<16),
                (uint32_t)__bfloat16_as_ushort(h2) | ((uint32_t)__bfloat16_as_ushort(h3)<<16));
            *(uint2*)(sBl+off) = make_uint2(
                (uint32_t)__bfloat16_as_ushort(l0h) | ((uint32_t)__bfloat16_as_ushort(l1h)<<16),
                (uint32_t)__bfloat16_as_ushort(l2h) | ((uint32_t)__bfloat16_as_ushort(l3h)<<16));
        }
        __syncthreads();
        int lr = lane & 15, lk = (lane >> 4) << 3;
        int brr = lane & 7, bkk = ((lane >> 3) & 1) << 3;
        uint32_t pAh = smem_u32(sAh) + (uint32_t)((m0+lr)*ASTR + lk)*2;
        uint32_t pAl = smem_u32(sAl) + (uint32_t)((m0+lr)*ASTR + lk)*2;
        uint32_t pBh = smem_u32(sBh) + (uint32_t)((n0+brr)*ASTR + bkk)*2;
        uint32_t pBl = smem_u32(sBl) + (uint32_t)((n0+brr)*ASTR + bkk)*2;
        #pragma unroll
        for (int ks = 0; ks < 32; ks += 16) {
            uint32_t ah[4][4], al[4][4], bh[J][2], bl[J][2];
            #pragma unroll
            for (int i = 0; i < 4; i++) {
                uint32_t o = (uint32_t)(i*16*ASTR + ks)*2;
                LDSM_X4(ah[i], pAh + o);
                LDSM_X4(al[i], pAl + o);
            }
            #pragma unroll
            for (int j = 0; j < J; j++) {
                uint32_t o = (uint32_t)(j*8*ASTR + ks)*2;
                LDSM_X2(bh[j], pBh + o);
                LDSM_X2(bl[j], pBl + o);
            }
            #pragma unroll
            for (int i = 0; i < 4; i++)
                #pragma unroll
                for (int j = 0; j < J; j++) {
                    MMA_BF16(c[i][j], ah[i], bh[j]);
                    MMA_BF16(c[i][j], al[i], bh[j]);
                    MMA_BF16(c[i][j], ah[i], bl[j]);
                }
        }
        __syncthreads();
    }
    #pragma unroll
    for (int i = 0; i < 4; i++)
        #pragma unroll
        for (int j = 0; j < J; j++) {
            int n = bn + n0 + j*8 + tq*2;
            if (n >= N) continue;
            float b0 = bias ? bias[n] : 0.f;
            float b1 = bias ? bias[n+1] : 0.f;
            #pragma unroll
            for (int hh = 0; hh < 2; hh++) {
                int gm = bm + m0 + i*16 + gq + hh*8;
                if (gm >= M) continue;
                float v0 = c[i][j][hh*2+0] + b0;
                float v1 = c[i][j][hh*2+1] + b1;
                if (act == 1) {
                    v0 = (v0 > 20.f) ? v0 : log1pf(__expf(v0));
                    v1 = (v1 > 20.f) ? v1 : log1pf(__expf(v1));
                }
                *(float2*)(C + (size_t)gm*ldc + n) = make_float2(v0, v1);
            }
        }
}

// ---------------- transpose (B,D,L)->(B,L,D) with bf16 split out ------------
__global__ void transpose_split(const float* __restrict__ src,
                                __nv_bfloat16* __restrict__ dh,
                                __nv_bfloat16* __restrict__ dl, int L, int D) {
    __shared__ float s[32][33];
    int b  = blockIdx.z;
    int d0 = blockIdx.y * 32;
    int l0 = blockIdx.x * 32;
    int tx = threadIdx.x, ty = threadIdx.y;
    #pragma unroll
    for (int i = 0; i < 32; i += 8) {
        int d = d0 + ty + i, l = l0 + tx;
        if (l < L) s[ty+i][tx] = src[((size_t)b*D + d)*L + l];
    }
    __syncthreads();
    #pragma unroll
    for (int i = 0; i < 32; i += 8) {
        int l = l0 + ty + i, d = d0 + tx;
        if (l < L) {
            float v = s[tx][ty+i];
            __nv_bfloat16 h, lo; splitw(v, h, lo);
            size_t o = ((size_t)b*L + l)*D + d;
            dh[o] = h; dl[o] = lo;
        }
    }
}

// ---------------- transpose (B,L,Dm)->(B,Dm,L) (outputs) ----------------
__global__ void transpose_ld(const float* __restrict__ src, float* __restrict__ dst,
                             int L) {
    __shared__ float s[32][33];
    int b  = blockIdx.z;
    int d0 = blockIdx.y * 32;
    int l0 = blockIdx.x * 32;
    int tx = threadIdx.x, ty = threadIdx.y;
    #pragma unroll
    for (int i = 0; i < 32; i += 8) {
        int l = l0 + ty + i, d = d0 + tx;
        if (l < L) s[ty+i][tx] = src[((size_t)b*L + l)*Dm + d];
    }
    __syncthreads();
    #pragma unroll
    for (int i = 0; i < 32; i += 8) {
        int d = d0 + ty + i, l = l0 + tx;
        if (l < L) dst[((size_t)b*Dm + d)*L + l] = s[tx][ty+i];
    }
}

// ---------------- fold BN into stem weights + split ----------------
__global__ void wprep(const float* __restrict__ w, const float* __restrict__ pb,
                      const float* __restrict__ bg, const float* __restrict__ bb,
                      const float* __restrict__ bm, const float* __restrict__ bv,
                      __nv_bfloat16* __restrict__ wh, __nv_bfloat16* __restrict__ wl,
                      float* __restrict__ b2) {
    int idx = blockIdx.x*256 + threadIdx.x;
    if (idx >= Dm*CIN) return;
    int o = idx / CIN, c = idx % CIN;
    float sc = rsqrtf(bv[o] + 1e-5f) * bg[o];
    __nv_bfloat16 h, l; splitw(w[idx]*sc, h, l);
    wh[idx] = h; wl[idx] = l;
    if (c == 0) b2[o] = bb[o] - bm[o]*sc + pb[o]*sc;
}

// ---------------- generic fp32 -> bf16 hi/lo split ----------------
__global__ void wsplit(const float* __restrict__ w, __nv_bfloat16* __restrict__ wh,
                       __nv_bfloat16* __restrict__ wl, int n) {
    int i = blockIdx.x*256 + threadIdx.x;
    if (i >= n) return;
    __nv_bfloat16 h, l; splitw(w[i], h, l);
    wh[i] = h; wl[i] = l;
}

// ---------------- row LayerNorm over D=192, bf16 hi/lo out ----------------
__global__ void ln_row(const float* __restrict__ xin, const float* __restrict__ g,
                       const float* __restrict__ bb,
                       __nv_bfloat16* __restrict__ oh, __nv_bfloat16* __restrict__ ol) {
    int warp = threadIdx.x >> 5, lane = threadIdx.x & 31;
    int row = blockIdx.x*8 + warp;
    const float* xr = xin + (size_t)row*Dm;
    float v[6]; float sum = 0.f, sq = 0.f;
    #pragma unroll
    for (int j = 0; j < 6; j++) { v[j] = xr[lane + 32*j]; sum += v[j]; sq += v[j]*v[j]; }
    #pragma unroll
    for (int o = 16; o > 0; o >>= 1) {
        sum += __shfl_xor_sync(0xffffffffu, sum, o);
        sq  += __shfl_xor_sync(0xffffffffu, sq,  o);
    }
    float mu = sum * (1.f/Dm);
    float var = sq * (1.f/Dm) - mu*mu;
    float rs = rsqrtf(var + 1e-5f);
    size_t ro = (size_t)row*Dm;
    #pragma unroll
    for (int j = 0; j < 6; j++) {
        int cidx = lane + 32*j;
        float val = (v[j]-mu)*rs*g[cidx] + bb[cidx];
        __nv_bfloat16 h, l; splitw(val, h, l);
        oh[ro + cidx] = h; ol[ro + cidx] = l;
    }
}

// ---------------- causal depthwise conv + SiLU, bf16 hi/lo out --------------
__global__ __launch_bounds__(384) void conv_silu2(const float* __restrict__ xz,
                                                  const float* __restrict__ w,
                                                  const float* __restrict__ cb,
                                                  __nv_bfloat16* __restrict__ oh,
                                                  __nv_bfloat16* __restrict__ ol, int L) {
    __shared__ float sx[19*384];
    int ntile = L / 16;
    int b  = blockIdx.x / ntile;
    int l0 = (blockIdx.x % ntile) * 16;
    for (int idx = threadIdx.x; idx < 19*384; idx += 384) {
        int r = idx / 384, e = idx % 384;
        int l = l0 - 3 + r;
        sx[idx] = (l >= 0) ? xz[((size_t)b*L + l)*(2*DIN) + e] : 0.f;
    }
    __syncthreads();
    int e = threadIdx.x;
    float4 wv = *(const float4*)(w + e*4);
    float cbe = cb[e];
    #pragma unroll 4
    for (int li = 0; li < 16; li++) {
        float acc = cbe;
        acc = fmaf(sx[(li+0)*384 + e], wv.x, acc);
        acc = fmaf(sx[(li+1)*384 + e], wv.y, acc);
        acc = fmaf(sx[(li+2)*384 + e], wv.z, acc);
        acc = fmaf(sx[(li+3)*384 + e], wv.w, acc);
        float sg = 1.f / (1.f + __expf(-acc));
        float val = acc * sg;
        __nv_bfloat16 h, l; splitw(val, h, l);
        size_t o = ((size_t)b*L + l0 + li)*DIN + e;
        oh[o] = h; ol[o] = l;
    }
}

// ---------------- chunked selective scan ----------------
__global__ void scan_chunk_local(const float* __restrict__ dt,
                                 const __nv_bfloat16* __restrict__ xih,
                                 const __nv_bfloat16* __restrict__ xil,
                                 const float* __restrict__ proj, const float* __restrict__ A_log,
                                 float* __restrict__ Pc, float* __restrict__ Hc,
                                 int L, int NCH) {
    int b  = blockIdx.x / (DIN/8);
    int ch = blockIdx.x % (DIN/8);
    int chunk = blockIdx.y;
    int e = ch*8 + (threadIdx.x >> 4);
    int n = threadIdx.x & 15;
    float A = -expf(A_log[e*NSz + n]);
    float h = 0.f, P = 1.f;
    int l0 = chunk*64;
    int lend = min(l0 + 64, L);
    size_t base_de = (size_t)b*L*DIN + e;
    size_t base_p  = (size_t)b*L*44 + DTRz + n;
    for (int l = l0; l < lend; l++) {
        size_t ide = base_de + (size_t)l*DIN;
        float tdt = dt[ide];
        float txi = __bfloat162float(xih[ide]) + __bfloat162float(xil[ide]);
        float tB  = proj[base_p + (size_t)l*44];
        float dA = __expf(tdt * A);
        h = fmaf(dA, h, tdt*txi*tB);
        P *= dA;
    }
    size_t idx = ((size_t)(b*NCH + chunk)*DIN + e)*NSz + n;
    Pc[idx] = P;
    Hc[idx] = h;
}

__global__ void scan_chunk_prefix(const float* __restrict__ Pc, const float* __restrict__ Hc,
                                  float* __restrict__ Hin, int NCH) {
    int i = blockIdx.x*blockDim.x + threadIdx.x;
    int b = i / (DIN*NSz);
    int inner = i % (DIN*NSz);
    float h = 0.f;
    for (int c = 0; c < NCH; c++) {
        size_t idx = (size_t)(b*NCH + c)*(DIN*NSz) + inner;
        Hin[idx] = h;
        h = fmaf(Pc[idx], h, Hc[idx]);
    }
}

__global__ void scan_chunk_final(const float* __restrict__ dt,
                                 const __nv_bfloat16* __restrict__ xih,
                                 const __nv_bfloat16* __restrict__ xil,
                                 const float* __restrict__ proj, const float* __restrict__ xz,
                                 const float* __restrict__ A_log, const float* __restrict__ Dskip,
                                 const float* __restrict__ Hin,
                                 __nv_bfloat16* __restrict__ yh, __nv_bfloat16* __restrict__ yl,
                                 int L, int NCH) {
    int b  = blockIdx.x / (DIN/8);
    int ch = blockIdx.x % (DIN/8);
    int chunk = blockIdx.y;
    int e = ch*8 + (threadIdx.x >> 4);
    int n = threadIdx.x & 15;
    float A  = -expf(A_log[e*NSz + n]);
    float Dk = Dskip[e];
    size_t sidx = ((size_t)(b*NCH + chunk)*DIN + e)*NSz + n;
    float h = Hin[sidx];
    int l0 = chunk*64;
    int lend = min(l0 + 64, L);
    size_t base_de = (size_t)b*L*DIN + e;
    size_t base_p  = (size_t)b*L*44;
    size_t base_z  = (size_t)b*L*(2*DIN) + DIN + e;
    for (int l = l0; l < lend; l++) {
        size_t ide = base_de + (size_t)l*DIN;
        float tdt = dt[ide];
        float txi = __bfloat162float(xih[ide]) + __bfloat162float(xil[ide]);
        float tB  = proj[base_p + (size_t)l*44 + DTRz + n];
        float tC  = proj[base_p + (size_t)l*44 + DTRz + NSz + n];
        float dA = __expf(tdt * A);
        h = fmaf(dA, h, tdt*txi*tB);
        float p = h * tC;
        p += __shfl_xor_sync(0xffffffffu, p, 8);
        p += __shfl_xor_sync(0xffffffffu, p, 4);
        p += __shfl_xor_sync(0xffffffffu, p, 2);
        p += __shfl_xor_sync(0xffffffffu, p, 1);
        if (n == 0) {
            float zv = xz[base_z + (size_t)l*(2*DIN)];
            float sz = zv / (1.f + __expf(-zv));
            float val = (p + Dk*txi) * sz;
            __nv_bfloat16 hh, ll; splitw(val, hh, ll);
            yh[ide] = hh; yl[ide] = ll;
        }
    }
}

// ---------------- 2x2 maxpool on (B,L,D) ----------------
__global__ void maxpool2(const float* __restrict__ in, float* __restrict__ out) {
    int i = blockIdx.x*blockDim.x + threadIdx.x;
    if (i >= Bz*L1z*Dm) return;
    int d = i % Dm;
    int l = (i / Dm) % L1z;
    int b = i / (Dm * L1z);
    int ho = l / 28, wo = l % 28;
    size_t base = ((size_t)b*L0z + (2*ho)*56 + 2*wo)*Dm + d;
    float v = fmaxf(fmaxf(in[base], in[base + Dm]),
                    fmaxf(in[base + 56*Dm], in[base + 57*Dm]));
    out[i] = v;
}

// ---------------- host ----------------
extern "C" void kernel_launch(void* const* d_in, const int* in_sizes, int n_in,
                              void* d_out, int out_size) {
    const float* x      = (const float*)d_in[0];
    const float* proj_w = (const float*)d_in[1];
    const float* proj_b = (const float*)d_in[2];
    const float* bn_g   = (const float*)d_in[3];
    const float* bn_b   = (const float*)d_in[4];
    const float* bn_mean= (const float*)d_in[5];
    const float* bn_var = (const float*)d_in[6];
    const float* ln_g   = (const float*)d_in[7];
    const float* ln_b   = (const float*)d_in[8];
    const float* Win    = (const float*)d_in[9];
    const float* b_in   = (const float*)d_in[10];
    const float* conv_w = (const float*)d_in[11];
    const float* conv_b = (const float*)d_in[12];
    const float* Wx     = (const float*)d_in[13];
    const float* Wdt    = (const float*)d_in[14];
    const float* bdt    = (const float*)d_in[15];
    const float* A_log  = (const float*)d_in[16];
    const float* Dskip  = (const float*)d_in[17];
    const float* Wout   = (const float*)d_in[18];
    const float* bout   = (const float*)d_in[19];
    float* out = (float*)d_out;

    float *px, *ppool, *pxz, *pproj, *pdt, *pblk, *pPc, *pHc, *pHin, *pb2;
    __nv_bfloat16 *phh,*phl,*pxih,*pxil,*pyh,*pyl,*pWinh,*pWinl,*pWxh,*pWxl,*pWouth,*pWoutl,*pw2h,*pw2l;
    cudaGetSymbolAddress((void**)&px,    g_x);
    cudaGetSymbolAddress((void**)&ppool, g_pool);
    cudaGetSymbolAddress((void**)&pxz,   g_xz);
    cudaGetSymbolAddress((void**)&pproj, g_proj);
    cudaGetSymbolAddress((void**)&pdt,   g_dt);
    cudaGetSymbolAddress((void**)&pblk,  g_blk);
    cudaGetSymbolAddress((void**)&pPc,   g_Pc);
    cudaGetSymbolAddress((void**)&pHc,   g_Hc);
    cudaGetSymbolAddress((void**)&pHin,  g_Hin);
    cudaGetSymbolAddress((void**)&pb2,   g_b2);
    cudaGetSymbolAddress((void**)&phh,   g_hh);
    cudaGetSymbolAddress((void**)&phl,   g_hl);
    cudaGetSymbolAddress((void**)&pxih,  g_xih);
    cudaGetSymbolAddress((void**)&pxil,  g_xil);
    cudaGetSymbolAddress((void**)&pyh,   g_yh);
    cudaGetSymbolAddress((void**)&pyl,   g_yl);
    cudaGetSymbolAddress((void**)&pWinh, g_Winh);
    cudaGetSymbolAddress((void**)&pWinl, g_Winl);
    cudaGetSymbolAddress((void**)&pWxh,  g_Wxh);
    cudaGetSymbolAddress((void**)&pWxl,  g_Wxl);
    cudaGetSymbolAddress((void**)&pWouth,g_Wouth);
    cudaGetSymbolAddress((void**)&pWoutl,g_Woutl);
    cudaGetSymbolAddress((void**)&pw2h,  g_w2h);
    cudaGetSymbolAddress((void**)&pw2l,  g_w2l);

    // ---- weight pre-splits ----
    wprep<<<(Dm*CIN + 255)/256, 256>>>(proj_w, proj_b, bn_g, bn_b, bn_mean, bn_var, pw2h, pw2l, pb2);
    wsplit<<<(3*2*DIN*Dm + 255)/256, 256>>>(Win,  pWinh,  pWinl,  3*2*DIN*Dm);
    wsplit<<<(3*44*DIN   + 255)/256, 256>>>(Wx,   pWxh,   pWxl,   3*44*DIN);
    wsplit<<<(3*Dm*DIN   + 255)/256, 256>>>(Wout, pWouth, pWoutl, 3*Dm*DIN);

    // ---- stem: transpose+split x to (B,L,96) bf16, GEMM -> px (B,L,192) fp32
    transpose_split<<<dim3(L0z/32, CIN/32, Bz), dim3(32,8)>>>(x, pxih, pxil, L0z, CIN);
    bgemm_bf<64><<<dim3(Dm/64, BL0/128), 256>>>(
        pxih, pxil, CIN, pw2h, pw2l, CIN, pb2, px, Dm, BL0, Dm, CIN, 0);

    auto run_block = [&](int i, const float* xin, int L, float* dst, int addC) {
        int BLc = Bz * L;
        int NCH = (L + 63) / 64;
        int mtiles = (BLc + 127) / 128;

        ln_row<<<BLc/8, 256>>>(xin, ln_g + i*Dm, ln_b + i*Dm, phh, phl);

        // in-proj: (BLc x 192) * (768 x 192)^T  [BN=128]
        bgemm_bf<128><<<dim3((2*DIN)/128, mtiles), 256>>>(
            phh, phl, Dm, pWinh + (size_t)i*2*DIN*Dm, pWinl + (size_t)i*2*DIN*Dm, Dm,
            b_in + i*2*DIN, pxz, 2*DIN, BLc, 2*DIN, Dm, 0);

        conv_silu2<<<Bz*(L/16), 384>>>(pxz, conv_w + i*DIN*KC, conv_b + i*DIN, pxih, pxil, L);

        // x-proj: (BLc x 384) * (44 x 384)^T  [BN=64]
        bgemm_bf<64><<<dim3(1, mtiles), 256>>>(
            pxih, pxil, DIN, pWxh + (size_t)i*44*DIN, pWxl + (size_t)i*44*DIN, DIN,
            nullptr, pproj, 44, BLc, 44, DIN, 0);

        // dt-proj + softplus: (BLc x 12) * (384 x 12)^T  (fp32-input path)
        bgemm_f<<<dim3(DIN/64, mtiles), 256>>>(
            pproj, 44, Wdt + (size_t)i*DIN*DTRz, DTRz,
            bdt + i*DIN, pdt, DIN, BLc, DIN, DTRz, 1);

        dim3 gsc(Bz*(DIN/8), NCH);
        scan_chunk_local<<<gsc, 128>>>(pdt, pxih, pxil, pproj,
                                       A_log + (size_t)i*DIN*NSz, pPc, pHc, L, NCH);
        scan_chunk_prefix<<<(Bz*DIN*NSz)/256, 256>>>(pPc, pHc, pHin, NCH);
        scan_chunk_final<<<gsc, 128>>>(pdt, pxih, pxil, pproj, pxz,
                                       A_log + (size_t)i*DIN*NSz, Dskip + i*DIN,
                                       pHin, pyh, pyl, L, NCH);

        // out-proj: (BLc x 384) * (192 x 384)^T  [BN=64], residual via addC
        bgemm_bf<64><<<dim3(Dm/64, mtiles), 256>>>(
            pyh, pyl, DIN, pWouth + (size_t)i*Dm*DIN, pWoutl + (size_t)i*Dm*DIN, DIN,
            bout + i*Dm, dst, Dm, BLc, Dm, DIN, addC);
    };

    run_block(0, px, L0z, px, 1);      // x += blk0(x)
    run_block(1, px, L0z, px, 1);      // x += blk1(x)

    // skip output: (B,L0,D) -> (B,D,L0)
    transpose_ld<<<dim3(L0z/32, Dm/32, Bz), dim3(32,8)>>>(px, out + (size_t)Bz*Dm*L1z, L0z);

    maxpool2<<<(Bz*L1z*Dm + 255)/256, 256>>>(px, ppool);
    run_block(2, ppool, L1z, pblk, 0);

    // final output: (B,L1,D) -> (B,D,L1)
    transpose_ld<<<dim3((L1z+31)/32, Dm/32, Bz), dim3(32,8)>>>(pblk, out, L1z);
}

// round 15
// speedup vs baseline: 1.2439x; 1.2439x over previous
#include <cuda_runtime.h>
#include <cuda_bf16.h>
#include <cstdint>

#define Dm   192
#define DIN  384
#define NSz  16
#define DTRz 12
#define KC   4
#define CIN  96
#define Bz   2
#define L0z  3136
#define L1z  784
#define BL0  (Bz*L0z)
#define NCHMAX 49
#define ASTR 40   // smem row stride in bf16 elements (conflict-free)

// ---------------- static scratch (no allocs allowed) ----------------
__device__ float g_x   [Bz*L0z*Dm];      // activation (B, L, D)
__device__ float g_h   [BL0*Dm];         // xT for stem, then layernorm output (B*L, D)
__device__ float g_xz  [BL0*2*DIN];
__device__ float g_xi  [BL0*DIN];
__device__ float g_proj[BL0*44];
__device__ float g_dt  [BL0*DIN];
__device__ float g_y   [BL0*DIN];
__device__ float g_blk [BL0*Dm];
__device__ float g_Pc  [Bz*NCHMAX*DIN*NSz];
__device__ float g_Hc  [Bz*NCHMAX*DIN*NSz];
__device__ float g_w2  [Dm*CIN];         // BN-folded stem weight
__device__ float g_b2  [Dm];             // BN-folded stem bias

#define MMA_BF16(c, a, b)                                                     \
    asm volatile("mma.sync.aligned.m16n8k16.row.col.f32.bf16.bf16.f32 "       \
        "{%0,%1,%2,%3},{%4,%5,%6,%7},{%8,%9},{%0,%1,%2,%3};"                  \
        : "+f"((c)[0]), "+f"((c)[1]), "+f"((c)[2]), "+f"((c)[3])              \
        : "r"((a)[0]), "r"((a)[1]), "r"((a)[2]), "r"((a)[3]),                 \
          "r"((b)[0]), "r"((b)[1]))

__device__ __forceinline__ uint32_t pack2(__nv_bfloat16 a, __nv_bfloat16 b) {
    return (uint32_t)__bfloat16_as_ushort(a) | ((uint32_t)__bfloat16_as_ushort(b) << 16);
}
__device__ __forceinline__ void split2(float x, float y, uint32_t& hi, uint32_t& lo) {
    __nv_bfloat16 hx = __float2bfloat16(x), hy = __float2bfloat16(y);
    __nv_bfloat16 lx = __float2bfloat16(x - __bfloat162float(hx));
    __nv_bfloat16 ly = __float2bfloat16(y - __bfloat162float(hy));
    hi = pack2(hx, hy);
    lo = pack2(lx, ly);
}

// ============ bf16x3 tensor-core GEMM: C = A(M,K)*B(N,K)^T + bias ============
// (exact R12 kernel — proven 557.8us config)
// BM=128, BN template (64/128), BK=32, 256 threads, 8 warps as 2m x 4n.
// 3-term split: AhBh + AlBh + AhBl. addC: C += result (residual fusion).
template<int BN>
__global__ __launch_bounds__(256) void bgemm(
        const float* __restrict__ A, int lda,
        const float* __restrict__ B, int ldb,
        const float* __restrict__ bias,
        float* __restrict__ C, int ldc,
        int M, int N, int K, int act, int addC) {
    constexpr int J = BN / 32;     // n-blocks per warp; also B staging iters
    __shared__ __align__(16) uint16_t sAh[128*ASTR];
    __shared__ __align__(16) uint16_t sAl[128*ASTR];
    __shared__ __align__(16) uint16_t sBh[BN*ASTR];
    __shared__ __align__(16) uint16_t sBl[BN*ASTR];

    int bm = blockIdx.y * 128, bn = blockIdx.x * BN;
    int tid  = threadIdx.x;
    int lane = tid & 31;
    int w    = tid >> 5;
    int m0 = (w & 1) * 64;
    int n0 = (w >> 1) * (BN/4);
    int gq = lane >> 2;
    int tq = lane & 3;

    float c[4][J][4];
    #pragma unroll
    for (int i = 0; i < 4; i++)
        #pragma unroll
        for (int j = 0; j < J; j++)
            #pragma unroll
            for (int t = 0; t < 4; t++) c[i][j][t] = 0.f;

    float4 pa[4], pb[J];
    const float4 z4 = make_float4(0.f,0.f,0.f,0.f);

    auto ldA = [&](int k0) {
        #pragma unroll
        for (int it = 0; it < 4; it++) {
            int idx = tid + it*256;
            int r = idx >> 3, q = idx & 7;
            int gm = bm + r, gk = k0 + q*4;
            pa[it] = (gm < M && gk < K) ? *(const float4*)(A + (size_t)gm*lda + gk) : z4;
        }
    };
    auto ldB = [&](int k0) {
        #pragma unroll
        for (int it = 0; it < J; it++) {
            int idx = tid + it*256;
            int r = idx >> 3, q = idx & 7;
            int gn = bn + r, gk = k0 + q*4;
            pb[it] = (gn < N && gk < K) ? *(const float4*)(B + (size_t)gn*ldb + gk) : z4;
        }
    };
    auto stA = [&]() {
        #pragma unroll
        for (int it = 0; it < 4; it++) {
            int idx = tid + it*256;
            int r = idx >> 3, q = idx & 7;
            uint32_t h0, l0, h1, l1;
            split2(pa[it].x, pa[it].y, h0, l0);
            split2(pa[it].z, pa[it].w, h1, l1);
            int off = r*ASTR + q*4;
            *(uint2*)(sAh + off) = make_uint2(h0, h1);
            *(uint2*)(sAl + off) = make_uint2(l0, l1);
        }
    };
    auto stB = [&]() {
        #pragma unroll
        for (int it = 0; it < J; it++) {
            int idx = tid + it*256;
            int r = idx >> 3, q = idx & 7;
            uint32_t h0, l0, h1, l1;
            split2(pb[it].x, pb[it].y, h0, l0);
            split2(pb[it].z, pb[it].w, h1, l1);
            int off = r*ASTR + q*4;
            *(uint2*)(sBh + off) = make_uint2(h0, h1);
            *(uint2*)(sBl + off) = make_uint2(l0, l1);
        }
    };

    int nst = (K + 31) / 32;
    ldA(0); ldB(0);
    for (int s = 0; s < nst; s++) {
        stA(); stB();
        __syncthreads();
        if (s + 1 < nst) { ldA((s+1)*32); ldB((s+1)*32); }

        #pragma unroll
        for (int ks = 0; ks < 32; ks += 16) {
            uint32_t ah[4][4], al[4][4], bh[J][2], bl[J][2];
            #pragma unroll
            for (int i = 0; i < 4; i++) {
                int mb = m0 + i*16 + gq;
                int o0 = mb*ASTR + 2*tq + ks;
                int o1 = (mb+8)*ASTR + 2*tq + ks;
                ah[i][0] = *(const uint32_t*)(sAh + o0);
                ah[i][1] = *(const uint32_t*)(sAh + o1);
                ah[i][2] = *(const uint32_t*)(sAh + o0 + 8);
                ah[i][3] = *(const uint32_t*)(sAh + o1 + 8);
                al[i][0] = *(const uint32_t*)(sAl + o0);
                al[i][1] = *(const uint32_t*)(sAl + o1);
                al[i][2] = *(const uint32_t*)(sAl + o0 + 8);
                al[i][3] = *(const uint32_t*)(sAl + o1 + 8);
            }
            #pragma unroll
            for (int j = 0; j < J; j++) {
                int nb = n0 + j*8 + gq;
                int o = nb*ASTR + 2*tq + ks;
                bh[j][0] = *(const uint32_t*)(sBh + o);
                bh[j][1] = *(const uint32_t*)(sBh + o + 8);
                bl[j][0] = *(const uint32_t*)(sBl + o);
                bl[j][1] = *(const uint32_t*)(sBl + o + 8);
            }
            #pragma unroll
            for (int i = 0; i < 4; i++)
                #pragma unroll
                for (int j = 0; j < J; j++) {
                    MMA_BF16(c[i][j], ah[i], bh[j]);
                    MMA_BF16(c[i][j], al[i], bh[j]);
                    MMA_BF16(c[i][j], ah[i], bl[j]);
                }
        }
        __syncthreads();
    }

    // ---- epilogue ----
    #pragma unroll
    for (int i = 0; i < 4; i++) {
        #pragma unroll
        for (int j = 0; j < J; j++) {
            int n = bn + n0 + j*8 + tq*2;
            if (n >= N) continue;
            float b0 = bias ? bias[n]   : 0.f;
            float b1 = bias ? bias[n+1] : 0.f;
            #pragma unroll
            for (int hh = 0; hh < 2; hh++) {
                int gm = bm + m0 + i*16 + gq + hh*8;
                if (gm >= M) continue;
                float v0 = c[i][j][hh*2 + 0] + b0;
                float v1 = c[i][j][hh*2 + 1] + b1;
                float* cp = C + (size_t)gm*ldc + n;
                if (addC) {
                    float2 old = *(float2*)cp;
                    v0 += old.x; v1 += old.y;
                } else if (act == 1) {
                    v0 = (v0 > 20.f) ? v0 : log1pf(__expf(v0));
                    v1 = (v1 > 20.f) ? v1 : log1pf(__expf(v1));
                }
                *(float2*)cp = make_float2(v0, v1);
            }
        }
    }
}

// ---------------- transpose (B,D,L)->(B,L,D), generic D (mult of 32) --------
__global__ void transpose_dl(const float* __restrict__ src, float* __restrict__ dst,
                             int L, int D) {
    __shared__ float s[32][33];
    int b  = blockIdx.z;
    int d0 = blockIdx.y * 32;
    int l0 = blockIdx.x * 32;
    int tx = threadIdx.x, ty = threadIdx.y;
    #pragma unroll
    for (int i = 0; i < 32; i += 8) {
        int d = d0 + ty + i, l = l0 + tx;
        if (l < L) s[ty+i][tx] = src[((size_t)b*D + d)*L + l];
    }
    __syncthreads();
    #pragma unroll
    for (int i = 0; i < 32; i += 8) {
        int l = l0 + ty + i, d = d0 + tx;
        if (l < L) dst[((size_t)b*L + l)*D + d] = s[tx][ty+i];
    }
}

// ---------------- transpose (B,L,Dm)->(B,Dm,L) (for outputs) ----------------
__global__ void transpose_ld(const float* __restrict__ src, float* __restrict__ dst,
                             int L) {
    __shared__ float s[32][33];
    int b  = blockIdx.z;
    int d0 = blockIdx.y * 32;
    int l0 = blockIdx.x * 32;
    int tx = threadIdx.x, ty = threadIdx.y;
    #pragma unroll
    for (int i = 0; i < 32; i += 8) {
        int l = l0 + ty + i, d = d0 + tx;
        if (l < L) s[ty+i][tx] = src[((size_t)b*L + l)*Dm + d];
    }
    __syncthreads();
    #pragma unroll
    for (int i = 0; i < 32; i += 8) {
        int d = d0 + ty + i, l = l0 + tx;
        if (l < L) dst[((size_t)b*Dm + d)*L + l] = s[tx][ty+i];
    }
}

// ---------------- fold BN into stem weights ----------------
__global__ void wprep(const float* __restrict__ w, const float* __restrict__ pb,
                      const float* __restrict__ bg, const float* __restrict__ bb,
                      const float* __restrict__ bm, const float* __restrict__ bv,
                      float* __restrict__ w2, float* __restrict__ b2) {
    int idx = blockIdx.x*256 + threadIdx.x;
    if (idx >= Dm*CIN) return;
    int o = idx / CIN, c = idx % CIN;
    float sc = rsqrtf(bv[o] + 1e-5f) * bg[o];
    w2[idx] = w[idx] * sc;
    if (c == 0) b2[o] = bb[o] - bm[o]*sc + pb[o]*sc;
}

// ---------------- row LayerNorm over D=192 on (B*L, D) ----------------
__global__ void ln_row(const float* __restrict__ xin, const float* __restrict__ g,
                       const float* __restrict__ bb, float* __restrict__ hout) {
    int warp = threadIdx.x >> 5, lane = threadIdx.x & 31;
    int row = blockIdx.x*8 + warp;
    const float* xr = xin + (size_t)row*Dm;
    float v[6]; float sum = 0.f, sq = 0.f;
    #pragma unroll
    for (int j = 0; j < 6; j++) { v[j] = xr[lane + 32*j]; sum += v[j]; sq += v[j]*v[j]; }
    #pragma unroll
    for (int o = 16; o > 0; o >>= 1) {
        sum += __shfl_xor_sync(0xffffffffu, sum, o);
        sq  += __shfl_xor_sync(0xffffffffu, sq,  o);
    }
    float mu = sum * (1.f/Dm);
    float var = sq * (1.f/Dm) - mu*mu;
    float rs = rsqrtf(var + 1e-5f);
    float* orow = hout + (size_t)row*Dm;
    #pragma unroll
    for (int j = 0; j < 6; j++) {
        int cidx = lane + 32*j;
        orow[cidx] = (v[j]-mu)*rs*g[cidx] + bb[cidx];
    }
}

// -------- fused 2x2 maxpool + row LayerNorm: (B,L0,D)->LN(pool) (B*L1,D) -----
__global__ void ln_pool(const float* __restrict__ xin, const float* __restrict__ g,
                        const float* __restrict__ bb, float* __restrict__ hout) {
    int warp = threadIdx.x >> 5, lane = threadIdx.x & 31;
    int row = blockIdx.x*8 + warp;          // 0 .. Bz*L1z-1
    int b = row / L1z;
    int l = row % L1z;
    int ho = l / 28, wo = l % 28;
    const float* p0 = xin + ((size_t)b*L0z + (2*ho)*56 + 2*wo)*Dm;
    float v[6]; float sum = 0.f, sq = 0.f;
    #pragma unroll
    for (int j = 0; j < 6; j++) {
        int cidx = lane + 32*j;
        float vv = fmaxf(fmaxf(p0[cidx], p0[Dm + cidx]),
                         fmaxf(p0[56*Dm + cidx], p0[57*Dm + cidx]));
        v[j] = vv; sum += vv; sq += vv*vv;
    }
    #pragma unroll
    for (int o = 16; o > 0; o >>= 1) {
        sum += __shfl_xor_sync(0xffffffffu, sum, o);
        sq  += __shfl_xor_sync(0xffffffffu, sq,  o);
    }
    float mu = sum * (1.f/Dm);
    float var = sq * (1.f/Dm) - mu*mu;
    float rs = rsqrtf(var + 1e-5f);
    float* orow = hout + (size_t)row*Dm;
    #pragma unroll
    for (int j = 0; j < 6; j++) {
        int cidx = lane + 32*j;
        orow[cidx] = (v[j]-mu)*rs*g[cidx] + bb[cidx];
    }
}

// ---------------- causal depthwise conv (K=4) + SiLU, smem-tiled ------------
__global__ __launch_bounds__(384) void conv_silu2(const float* __restrict__ xz,
                                                  const float* __restrict__ w,
                                                  const float* __restrict__ cb,
                                                  float* __restrict__ xo, int L) {
    __shared__ float sx[19*384];
    int ntile = L / 16;
    int b  = blockIdx.x / ntile;
    int l0 = (blockIdx.x % ntile) * 16;
    for (int idx = threadIdx.x; idx < 19*384; idx += 384) {
        int r = idx / 384, e = idx % 384;
        int l = l0 - 3 + r;
        sx[idx] = (l >= 0) ? xz[((size_t)b*L + l)*(2*DIN) + e] : 0.f;
    }
    __syncthreads();
    int e = threadIdx.x;
    float4 wv = *(const float4*)(w + e*4);
    float cbe = cb[e];
    #pragma unroll 4
    for (int li = 0; li < 16; li++) {
        float acc = cbe;
        acc = fmaf(sx[(li+0)*384 + e], wv.x, acc);
        acc = fmaf(sx[(li+1)*384 + e], wv.y, acc);
        acc = fmaf(sx[(li+2)*384 + e], wv.z, acc);
        acc = fmaf(sx[(li+3)*384 + e], wv.w, acc);
        float sg = 1.f / (1.f + __expf(-acc));
        xo[((size_t)b*L + l0 + li)*DIN + e] = acc * sg;
    }
}

// ---------------- chunked selective scan (2 kernels; lookback fused) --------
__global__ void scan_chunk_local(const float* __restrict__ dt, const float* __restrict__ xi,
                                 const float* __restrict__ proj, const float* __restrict__ A_log,
                                 float* __restrict__ Pc, float* __restrict__ Hc,
                                 int L, int NCH) {
    int b  = blockIdx.x / (DIN/8);
    int ch = blockIdx.x % (DIN/8);
    int chunk = blockIdx.y;
    int e = ch*8 + (threadIdx.x >> 4);
    int n = threadIdx.x & 15;
    float A = -expf(A_log[e*NSz + n]);
    float h = 0.f, P = 1.f;
    int l0 = chunk*64;
    int lend = min(l0 + 64, L);
    size_t base_de = (size_t)b*L*DIN + e;
    size_t base_p  = (size_t)b*L*44 + DTRz + n;
    for (int l = l0; l < lend; l++) {
        float tdt = dt[base_de + (size_t)l*DIN];
        float txi = xi[base_de + (size_t)l*DIN];
        float tB  = proj[base_p + (size_t)l*44];
        float dA = __expf(tdt * A);
        h = fmaf(dA, h, tdt*txi*tB);
        P *= dA;
    }
    size_t idx = ((size_t)(b*NCH + chunk)*DIN + e)*NSz + n;
    Pc[idx] = P;
    Hc[idx] = h;
}

// final pass: per-block lookback over prior chunks' (Pc,Hc), then recompute+emit
__global__ void scan_chunk_final(const float* __restrict__ dt, const float* __restrict__ xi,
                                 const float* __restrict__ proj, const float* __restrict__ xz,
                                 const float* __restrict__ A_log, const float* __restrict__ Dskip,
                                 const float* __restrict__ Pc, const float* __restrict__ Hc,
                                 float* __restrict__ y, int L, int NCH) {
    int b  = blockIdx.x / (DIN/8);
    int ch = blockIdx.x % (DIN/8);
    int chunk = blockIdx.y;
    int e = ch*8 + (threadIdx.x >> 4);
    int n = threadIdx.x & 15;
    float A  = -expf(A_log[e*NSz + n]);
    float Dk = Dskip[e];
    // lookback: fold prior chunk summaries into incoming state
    float h = 0.f;
    {
        size_t idx = ((size_t)b*NCH*DIN + e)*NSz + n;
        size_t step = (size_t)DIN*NSz;
        for (int cc = 0; cc < chunk; cc++) {
            h = fmaf(Pc[idx], h, Hc[idx]);
            idx += step;
        }
    }
    int l0 = chunk*64;
    int lend = min(l0 + 64, L);
    size_t base_de = (size_t)b*L*DIN + e;
    size_t base_p  = (size_t)b*L*44;
    size_t base_z  = (size_t)b*L*(2*DIN) + DIN + e;
    for (int l = l0; l < lend; l++) {
        float tdt = dt[base_de + (size_t)l*DIN];
        float txi = xi[base_de + (size_t)l*DIN];
        float tB  = proj[base_p + (size_t)l*44 + DTRz + n];
        float tC  = proj[base_p + (size_t)l*44 + DTRz + NSz + n];
        float dA = __expf(tdt * A);
        h = fmaf(dA, h, tdt*txi*tB);
        float p = h * tC;
        p += __shfl_xor_sync(0xffffffffu, p, 8);
        p += __shfl_xor_sync(0xffffffffu, p, 4);
        p += __shfl_xor_sync(0xffffffffu, p, 2);
        p += __shfl_xor_sync(0xffffffffu, p, 1);
        if (n == 0) {
            float zv = xz[base_z + (size_t)l*(2*DIN)];
            float sz = zv / (1.f + __expf(-zv));
            y[base_de + (size_t)l*DIN] = (p + Dk*txi) * sz;
        }
    }
}

// ---------------- host ----------------
extern "C" void kernel_launch(void* const* d_in, const int* in_sizes, int n_in,
                              void* d_out, int out_size) {
    const float* x      = (const float*)d_in[0];
    const float* proj_w = (const float*)d_in[1];
    const float* proj_b = (const float*)d_in[2];
    const float* bn_g   = (const float*)d_in[3];
    const float* bn_b   = (const float*)d_in[4];
    const float* bn_mean= (const float*)d_in[5];
    const float* bn_var = (const float*)d_in[6];
    const float* ln_g   = (const float*)d_in[7];
    const float* ln_b   = (const float*)d_in[8];
    const float* Win    = (const float*)d_in[9];
    const float* b_in   = (const float*)d_in[10];
    const float* conv_w = (const float*)d_in[11];
    const float* conv_b = (const float*)d_in[12];
    const float* Wx     = (const float*)d_in[13];
    const float* Wdt    = (const float*)d_in[14];
    const float* bdt    = (const float*)d_in[15];
    const float* A_log  = (const float*)d_in[16];
    const float* Dskip  = (const float*)d_in[17];
    const float* Wout   = (const float*)d_in[18];
    const float* bout   = (const float*)d_in[19];
    float* out = (float*)d_out;

    float *px, *ph, *pxz, *pxi, *pproj, *pdt, *py, *pblk, *pPc, *pHc, *pw2, *pb2;
    cudaGetSymbolAddress((void**)&px,    g_x);
    cudaGetSymbolAddress((void**)&ph,    g_h);
    cudaGetSymbolAddress((void**)&pxz,   g_xz);
    cudaGetSymbolAddress((void**)&pxi,   g_xi);
    cudaGetSymbolAddress((void**)&pproj, g_proj);
    cudaGetSymbolAddress((void**)&pdt,   g_dt);
    cudaGetSymbolAddress((void**)&py,    g_y);
    cudaGetSymbolAddress((void**)&pblk,  g_blk);
    cudaGetSymbolAddress((void**)&pPc,   g_Pc);
    cudaGetSymbolAddress((void**)&pHc,   g_Hc);
    cudaGetSymbolAddress((void**)&pw2,   g_w2);
    cudaGetSymbolAddress((void**)&pb2,   g_b2);

    // ---- stem: transpose x to (B,L,96), fold BN into weights, GEMM -> px (B,L,192)
    transpose_dl<<<dim3(L0z/32, CIN/32, Bz), dim3(32,8)>>>(x, ph, L0z, CIN);
    wprep<<<(Dm*CIN + 255)/256, 256>>>(proj_w, proj_b, bn_g, bn_b, bn_mean, bn_var, pw2, pb2);
    bgemm<64><<<dim3(Dm/64, (BL0+127)/128), 256>>>(
        ph, CIN, pw2, CIN, pb2, px, Dm, BL0, Dm, CIN, 0, 0);

    auto run_block = [&](int i, int L, float* dst, int addC, int pool) {
        int BLc = Bz * L;
        int NCH = (L + 63) / 64;
        int mtiles = (BLc + 127) / 128;

        if (pool) ln_pool<<<BLc/8, 256>>>(px, ln_g + i*Dm, ln_b + i*Dm, ph);
        else      ln_row <<<BLc/8, 256>>>(px, ln_g + i*Dm, ln_b + i*Dm, ph);

        // in-proj: (BLc x 192) * (768 x 192)^T  [BN=128]
        bgemm<128><<<dim3((2*DIN)/128, mtiles), 256>>>(
            ph, Dm, Win + (size_t)i*2*DIN*Dm, Dm,
            b_in + i*2*DIN, pxz, 2*DIN, BLc, 2*DIN, Dm, 0, 0);

        conv_silu2<<<Bz*(L/16), 384>>>(pxz, conv_w + i*DIN*KC, conv_b + i*DIN, pxi, L);

        // x-proj: (BLc x 384) * (44 x 384)^T  [BN=64]
        bgemm<64><<<dim3(1, mtiles), 256>>>(
            pxi, DIN, Wx + (size_t)i*44*DIN, DIN,
            nullptr, pproj, 44, BLc, 44, DIN, 0, 0);

        // dt-proj + softplus: (BLc x 12) * (384 x 12)^T  [BN=64]
        bgemm<64><<<dim3(DIN/64, mtiles), 256>>>(
            pproj, 44, Wdt + (size_t)i*DIN*DTRz, DTRz,
            bdt + i*DIN, pdt, DIN, BLc, DIN, DTRz, 1, 0);

        dim3 gsc(Bz*(DIN/8), NCH);
        scan_chunk_local<<<gsc, 128>>>(pdt, pxi, pproj,
                                       A_log + (size_t)i*DIN*NSz, pPc, pHc, L, NCH);
        scan_chunk_final<<<gsc, 128>>>(pdt, pxi, pproj, pxz,
                                       A_log + (size_t)i*DIN*NSz, Dskip + i*DIN,
                                       pPc, pHc, py, L, NCH);

        // out-proj: (BLc x 384) * (192 x 384)^T  [BN=64], residual fused via addC
        bgemm<64><<<dim3(Dm/64, mtiles), 256>>>(
            py, DIN, Wout + (size_t)i*Dm*DIN, DIN,
            bout + i*Dm, dst, Dm, BLc, Dm, DIN, 0, addC);
    };

    run_block(0, L0z, px, 1, 0);      // x += blk0(x)   (in-place residual)
    run_block(1, L0z, px, 1, 0);      // x += blk1(x)

    // skip output: (B,L0,D) -> (B,D,L0) into out's second region
    transpose_ld<<<dim3(L0z/32, Dm/32, Bz), dim3(32,8)>>>(px, out + (size_t)Bz*Dm*L1z, L0z);

    // block 2 on pooled input (maxpool fused into ln_pool)
    run_block(2, L1z, pblk, 0, 1);    // pblk = blk2(pool(x)) in (B,L1,D)

    // final output: (B,L1,D) -> (B,D,L1) into out's first region
    transpose_ld<<<dim3((L1z+31)/32, Dm/32, Bz), dim3(32,8)>>>(pblk, out, L1z);
}